// round 8
// baseline (speedup 1.0000x reference)
#include <cuda_runtime.h>
#include <cuda_bf16.h>
#include <cuda_fp16.h>
#include <cstdint>

// ---------------------------------------------------------------------------
// softplus( exp(-0.5*||x_i - c_j||^2) @ beta ),  N=40000, M=4000, D=32.
//
// R8: bf16 K=32 mma.sync GEMM + PACKED f16x2 exp epilogue:
//   seed  d = G_j + bx_i + 10          (MMA C-operand does the adds)
//   arg   = dot*log2e + G + bx + 10    (<= 10 always, Cauchy-Schwarz)
//   e2    = ex2.approx.f16x2(cvt.f16x2(d0,d1))   -- 2 exps per MUFU op
//   facc  = add.f16x2(facc, e2)        (16-term window, flushed to f32/tile)
//   out   = softplus( 2^-10 * sum )
// Halves the MUFU EX2 instruction count (the R7 binding pipe).
// Everything else (warp-pair center split, cp.async.bulk double buffering,
// in-kernel A-image build) as R7.
// ---------------------------------------------------------------------------

#define LOG2E 1.4426950408889634f
typedef unsigned long long ull;

constexpr int D    = 32;
constexpr int RC   = 96;        // rows per CTA
constexpr int NB   = 128;       // centers per tile
constexpr int MAXM = 8192;      // padded center capacity
constexpr int ROWB = 64;        // bytes per bf16 image row (32 bf16)

__device__ __align__(128) uint8_t g_cI[(size_t)MAXM * ROWB];  // c*log2e, bf16, swizzled
__device__ float g_G[MAXM];     // -0.5*||c||^2*log2e + log2(beta);  -1e30 pad

__device__ __forceinline__ uint32_t pack_bf2(float a, float b) {
    __nv_bfloat16 ha = __float2bfloat16(a), hb = __float2bfloat16(b);
    unsigned short ua = *reinterpret_cast<unsigned short*>(&ha);
    unsigned short ub = *reinterpret_cast<unsigned short*>(&hb);
    return (uint32_t)ua | ((uint32_t)ub << 16);
}

// ---- async copy / mbarrier -------------------------------------------------
__device__ __forceinline__ void mbar_init(uint32_t mb, int count) {
    asm volatile("mbarrier.init.shared.b64 [%0], %1;" :: "r"(mb), "r"(count) : "memory");
}
__device__ __forceinline__ void mbar_expect_tx(uint32_t mb, uint32_t bytes) {
    asm volatile("mbarrier.arrive.expect_tx.shared.b64 _, [%0], %1;"
                 :: "r"(mb), "r"(bytes) : "memory");
}
__device__ __forceinline__ void bulk_g2s(uint32_t sdst, const void* gsrc,
                                         uint32_t bytes, uint32_t mb) {
    asm volatile(
        "cp.async.bulk.shared::cta.global.mbarrier::complete_tx::bytes "
        "[%0], [%1], %2, [%3];"
        :: "r"(sdst), "l"(gsrc), "r"(bytes), "r"(mb) : "memory");
}
__device__ __forceinline__ void mbar_wait(uint32_t mb, uint32_t parity) {
    uint32_t done;
    asm volatile(
        "{\n\t.reg .pred p;\n\t"
        "mbarrier.try_wait.parity.acquire.cta.shared::cta.b64 p, [%1], %2;\n\t"
        "selp.b32 %0, 1, 0, p;\n\t}"
        : "=r"(done) : "r"(mb), "r"(parity) : "memory");
    if (!done) {
        asm volatile(
            "{\n\t.reg .pred P1;\n\t"
            "WL_%=:\n\t"
            "mbarrier.try_wait.parity.acquire.cta.shared::cta.b64 P1, [%0], %1, 0x989680;\n\t"
            "@P1 bra.uni WD_%=;\n\t"
            "bra.uni WL_%=;\n\t"
            "WD_%=:\n\t}"
            :: "r"(mb), "r"(parity) : "memory");
    }
}

// ---- warp MMA primitives ---------------------------------------------------
__device__ __forceinline__ void ldmx4(uint32_t& r0, uint32_t& r1,
                                      uint32_t& r2, uint32_t& r3, uint32_t addr) {
    asm volatile("ldmatrix.sync.aligned.m8n8.x4.shared.b16 {%0,%1,%2,%3}, [%4];"
                 : "=r"(r0), "=r"(r1), "=r"(r2), "=r"(r3) : "r"(addr));
}

__device__ __forceinline__ void mma16816(float& d0, float& d1, float& d2, float& d3,
                                         uint32_t a0, uint32_t a1, uint32_t a2, uint32_t a3,
                                         uint32_t b0, uint32_t b1) {
    asm volatile(
        "mma.sync.aligned.m16n8k16.row.col.f32.bf16.bf16.f32 "
        "{%0,%1,%2,%3}, {%4,%5,%6,%7}, {%8,%9}, {%0,%1,%2,%3};"
        : "+f"(d0), "+f"(d1), "+f"(d2), "+f"(d3)
        : "r"(a0), "r"(a1), "r"(a2), "r"(a3), "r"(b0), "r"(b1));
}

// packed exp2 of two f32 values (order inside the pair is irrelevant:
// both halves are summed into the same row accumulator)
__device__ __forceinline__ uint32_t ex2_f16x2(float a, float b) {
    uint32_t h;
    asm("cvt.rn.f16x2.f32 %0, %1, %2;" : "=r"(h) : "f"(a), "f"(b));
    asm("ex2.approx.f16x2 %0, %1;" : "=r"(h) : "r"(h));
    return h;
}
__device__ __forceinline__ uint32_t hadd2(uint32_t a, uint32_t b) {
    uint32_t r;
    asm("add.rn.f16x2 %0, %1, %2;" : "=r"(r) : "r"(a), "r"(b));
    return r;
}
__device__ __forceinline__ float hsum2f(uint32_t h) {
    __half2 v = *reinterpret_cast<__half2*>(&h);
    float2 f = __half22float2(v);
    return f.x + f.y;
}

// ---------------------------------------------------------------------------
// prep_c: one thread per HALF center row (16 floats). Writes the 64B bf16
// image row with chunk swizzle  phys_chunk = logical_chunk ^ ((j>>1)&3),
// and G_j (half 0 only). Padded rows: zero image, G = -1e30.
// ---------------------------------------------------------------------------
__global__ void prep_c(const float* __restrict__ c,
                       const float* __restrict__ beta, int M, int mpad) {
    int idx  = blockIdx.x * blockDim.x + threadIdx.x;
    int j    = idx >> 1;
    int half = idx & 1;
    if (j >= mpad) return;

    float v[16];
    if (j < M) {
        const float4* cp = reinterpret_cast<const float4*>(c + (size_t)j * D + half * 16);
        #pragma unroll
        for (int q = 0; q < 4; q++) {
            float4 t = cp[q];
            v[4 * q] = t.x; v[4 * q + 1] = t.y; v[4 * q + 2] = t.z; v[4 * q + 3] = t.w;
        }
    } else {
        #pragma unroll
        for (int k = 0; k < 16; k++) v[k] = 0.f;
    }
    float s = 0.f;
    #pragma unroll
    for (int k = 0; k < 16; k++) {
        s = fmaf(v[k], v[k], s);
        v[k] *= LOG2E;
    }
    s += __shfl_xor_sync(0xffffffffu, s, 1);   // full ||c||^2 (pair in same warp)

    uint32_t wd[8];
    #pragma unroll
    for (int k = 0; k < 8; k++) wd[k] = pack_bf2(v[2 * k], v[2 * k + 1]);

    const uint32_t key = ((uint32_t)j >> 1) & 3;
    uint8_t* base = g_cI + (size_t)j * ROWB;
    #pragma unroll
    for (int cch = 0; cch < 2; cch++) {
        uint32_t lch = (uint32_t)half * 2 + cch;
        uint4 u = make_uint4(wd[4 * cch], wd[4 * cch + 1], wd[4 * cch + 2], wd[4 * cch + 3]);
        *reinterpret_cast<uint4*>(base + ((lch ^ key) << 4)) = u;
    }

    if (half == 0)
        g_G[j] = (j < M) ? fmaf(-0.5f * LOG2E, s, log2f(beta[j])) : -1e30f;
}

// ---------------------------------------------------------------------------
// Main fused kernel: grid = ceil(N/96), 384 threads (12 warps).
// Warp pair (wp = w>>1) owns rows [wp*16, wp*16+16); half = w&1 selects which
// 64 centers of the 128-tile the warp processes.
// ---------------------------------------------------------------------------
constexpr int SA   = 0;
constexpr int SB0  = 6144;
constexpr int SB1  = 14336;
constexpr int SG0  = 22528;
constexpr int SG1  = 23040;
constexpr int SBX  = 23552;
constexpr int SRED = 23936;          // float[2][96]
constexpr int SMB  = 24704;          // mbF0 @+0, mbF1 @+8
constexpr int STOT = 24720;

__global__ void __launch_bounds__(384)
krr_main(const float* __restrict__ x, float* __restrict__ out, int N, int ntiles)
{
    __shared__ __align__(128) uint8_t smem[STOT];
    const uint32_t sbase = (uint32_t)__cvta_generic_to_shared(smem);

    const int tid  = threadIdx.x;
    const int w    = tid >> 5;
    const int lane = tid & 31;
    const int wp   = w >> 1;       // row group 0..5
    const int half = w & 1;        // center half 0/1

    const uint32_t mbF[2] = {sbase + SMB, sbase + SMB + 8};

    if (tid == 0) {
        mbar_init(mbF[0], 1);
        mbar_init(mbF[1], 1);
    }
    asm volatile("fence.proxy.async.shared::cta;" ::: "memory");
    __syncthreads();

    if (tid == 0) {
        mbar_expect_tx(mbF[0], NB * ROWB + NB * 4);
        bulk_g2s(sbase + SB0, g_cI, NB * ROWB, mbF[0]);
        bulk_g2s(sbase + SG0, g_G, NB * 4, mbF[0]);
        if (ntiles > 1) {
            mbar_expect_tx(mbF[1], NB * ROWB + NB * 4);
            bulk_g2s(sbase + SB1, g_cI + (size_t)NB * ROWB, NB * ROWB, mbF[1]);
            bulk_g2s(sbase + SG1, g_G + NB, NB * 4, mbF[1]);
        }
    }

    // ---- convert this CTA's 96 x-rows into the swizzled bf16 A image ------
    if (tid < 192) {
        int r    = tid >> 1;
        int hh   = tid & 1;
        int gr   = blockIdx.x * RC + r;
        if (gr > N - 1) gr = N - 1;

        float v[16];
        const float4* xp = reinterpret_cast<const float4*>(x + (size_t)gr * D + hh * 16);
        #pragma unroll
        for (int q = 0; q < 4; q++) {
            float4 t = xp[q];
            v[4 * q] = t.x; v[4 * q + 1] = t.y; v[4 * q + 2] = t.z; v[4 * q + 3] = t.w;
        }
        float s = 0.f;
        #pragma unroll
        for (int k = 0; k < 16; k++) s = fmaf(v[k], v[k], s);
        s += __shfl_xor_sync(0xffffffffu, s, 1);

        uint32_t wd[8];
        #pragma unroll
        for (int k = 0; k < 8; k++) wd[k] = pack_bf2(v[2 * k], v[2 * k + 1]);

        const uint32_t key = ((uint32_t)r >> 1) & 3;
        uint8_t* abase = smem + SA + r * ROWB;
        #pragma unroll
        for (int cch = 0; cch < 2; cch++) {
            uint32_t lch = (uint32_t)hh * 2 + cch;
            uint4 u = make_uint4(wd[4 * cch], wd[4 * cch + 1], wd[4 * cch + 2], wd[4 * cch + 3]);
            *reinterpret_cast<uint4*>(abase + ((lch ^ key) << 4)) = u;
        }
        if (hh == 0)
            *reinterpret_cast<float*>(smem + SBX + r * 4) = -0.5f * s * LOG2E;
    }
    __syncthreads();

    // ---- A fragments (once per warp) ----
    const uint32_t arow = (uint32_t)wp * 16 + (lane & 15);
    const uint32_t akey = (arow >> 1) & 3;
    uint32_t a[8];
    {
        uint32_t ad0 = sbase + SA + arow * ROWB + ((((uint32_t)(lane >> 4) + 0) ^ akey) << 4);
        uint32_t ad1 = sbase + SA + arow * ROWB + ((((uint32_t)(lane >> 4) + 2) ^ akey) << 4);
        ldmx4(a[0], a[1], a[2], a[3], ad0);   // k 0-15
        ldmx4(a[4], a[5], a[6], a[7], ad1);   // k 16-31
    }

    // per-row bias (+10 = global shift, undone at the end), in registers
    const float* bxsm = reinterpret_cast<const float*>(smem + SBX);
    const float bxlo = bxsm[wp * 16 + (lane >> 2)]     + 10.0f;
    const float bxhi = bxsm[wp * 16 + (lane >> 2) + 8] + 10.0f;

    // per-lane B address constant: row = lane&7, chunk = lane>>3 (swizzled)
    const uint32_t l7 = lane & 7;
    const uint32_t boff = l7 * ROWB + ((((uint32_t)lane >> 3) ^ ((l7 >> 1) & 3)) << 4);
    const uint32_t gbase = (uint32_t)half * 8;   // this warp's first group

    float rs_lo = 0.f, rs_hi = 0.f;

    for (int t = 0; t < ntiles; t++) {
        const int buf = t & 1;
        mbar_wait(mbF[buf], (t >> 1) & 1);

        const uint32_t sB = sbase + (buf ? SB1 : SB0);
        const float2* G2 = reinterpret_cast<const float2*>(smem + (buf ? SG1 : SG0));

        uint32_t facc01 = 0u, facc23 = 0u;   // f16x2 window accumulators

        #pragma unroll 4
        for (int gg = 0; gg < 8; gg++) {
            const uint32_t g = gbase + gg;
            uint32_t b0, b1, b2, b3;
            ldmx4(b0, b1, b2, b3, sB + g * (8 * ROWB) + boff);

            // seed with G + bx + 10: the mma C-operand performs the adds,
            // and arg = dot+G+bx+10 <= 10 (Cauchy-Schwarz) -> f16-safe.
            float2 Gp = G2[g * 4 + (lane & 3)];
            float d0 = Gp.x + bxlo, d1 = Gp.y + bxlo;
            float d2 = Gp.x + bxhi, d3 = Gp.y + bxhi;
            mma16816(d0, d1, d2, d3, a[0], a[1], a[2], a[3], b0, b1);
            mma16816(d0, d1, d2, d3, a[4], a[5], a[6], a[7], b2, b3);

            facc01 = hadd2(facc01, ex2_f16x2(d0, d1));
            facc23 = hadd2(facc23, ex2_f16x2(d2, d3));
        }

        rs_lo += hsum2f(facc01);   // flush 16-term f16 window to f32
        rs_hi += hsum2f(facc23);

        __syncthreads();
        if (tid == 0 && t + 2 < ntiles) {
            mbar_expect_tx(mbF[buf], NB * ROWB + NB * 4);
            bulk_g2s(sbase + (buf ? SB1 : SB0),
                     g_cI + (size_t)(t + 2) * NB * ROWB, NB * ROWB, mbF[buf]);
            bulk_g2s(sbase + (buf ? SG1 : SG0),
                     g_G + (size_t)(t + 2) * NB, NB * 4, mbF[buf]);
        }
    }

    // ---- reduce across the 4 column-lanes, deposit per-half partials ----
    rs_lo += __shfl_xor_sync(0xffffffffu, rs_lo, 1);
    rs_lo += __shfl_xor_sync(0xffffffffu, rs_lo, 2);
    rs_hi += __shfl_xor_sync(0xffffffffu, rs_hi, 1);
    rs_hi += __shfl_xor_sync(0xffffffffu, rs_hi, 2);

    float* red = reinterpret_cast<float*>(smem + SRED);
    const int lrow = wp * 16 + (lane >> 2);
    if ((lane & 3) == 0) red[half * 96 + lrow]     = rs_lo;
    if ((lane & 3) == 1) red[half * 96 + lrow + 8] = rs_hi;
    __syncthreads();

    // ---- combine halves, undo 2^10 shift, softplus, write ----
    if (tid < RC) {
        int r = blockIdx.x * RC + tid;
        if (r < N) {
            float s = 0.0009765625f * (red[tid] + red[96 + tid]);   // * 2^-10
            out[r] = s + log1pf(expf(-s));
        }
    }
}

// ---------------------------------------------------------------------------
extern "C" void kernel_launch(void* const* d_in, const int* in_sizes, int n_in,
                              void* d_out, int out_size) {
    const float* x    = (const float*)d_in[0];  // (N, 32)
    const float* c    = (const float*)d_in[1];  // (M, 32)
    const float* beta = (const float*)d_in[2];  // (M,)
    float* out = (float*)d_out;                 // (N,)

    const int M = in_sizes[2];
    const int N = out_size;

    int nct = (M + NB - 1) / NB;
    if (nct > MAXM / NB) nct = MAXM / NB;
    const int mpad = nct * NB;

    prep_c<<<(mpad * 2 + 255) / 256, 256>>>(c, beta, M, mpad);

    const int grid = (N + RC - 1) / RC;
    krr_main<<<grid, 384>>>(x, out, N, nct);
}

// round 9
// speedup vs baseline: 1.2305x; 1.2305x over previous
#include <cuda_runtime.h>
#include <cuda_fp16.h>
#include <cstdint>

// ---------------------------------------------------------------------------
// softplus( exp(-0.5*||x_i - c_j||^2) @ beta ),  N=40000, M=4000, D=32.
//
// R9: f16 K=32 mma.sync GEMM with **f16 accumulators** + packed f16x2 exp:
//   seed  d01 = (G'_{c0}, G'_{c1}) + (bx,bx)       [1 HADD2; G' = G + 10]
//   mma   d01 = f16( dot*log2e ) + seed            [D regs are native f16x2]
//   e01   = ex2.approx.f16x2(d01)                  [2 exps / MUFU op, NO cvt]
//   facc  = add.f16x2(facc, e01)                   [16-term window]
//   out   = softplus( 2^-10 * sum )
// This removes R8's cvt overhead entirely and genuinely halves MUFU ops
// (the binding pipe). Everything else (warp-pair center split, cp.async.bulk
// double buffering, in-kernel A-image build) as R7.
// ---------------------------------------------------------------------------

#define LOG2E 1.4426950408889634f
typedef unsigned long long ull;

constexpr int D    = 32;
constexpr int RC   = 96;        // rows per CTA
constexpr int NB   = 128;       // centers per tile
constexpr int MAXM = 8192;      // padded center capacity
constexpr int ROWB = 64;        // bytes per f16 image row (32 f16)

__device__ __align__(128) uint8_t g_cI[(size_t)MAXM * ROWB];  // f16(c*log2e), swizzled
__device__ __half g_Gh[MAXM];   // f16( -0.5*||c||^2*log2e + log2(beta) + 10 )

// pack two f32 into f16x2: lo -> bits[0:16], hi -> bits[16:32]
__device__ __forceinline__ uint32_t pack_hf2(float lo, float hi) {
    uint32_t h;
    asm("cvt.rn.f16x2.f32 %0, %1, %2;" : "=r"(h) : "f"(hi), "f"(lo));
    return h;
}

// ---- async copy / mbarrier -------------------------------------------------
__device__ __forceinline__ void mbar_init(uint32_t mb, int count) {
    asm volatile("mbarrier.init.shared.b64 [%0], %1;" :: "r"(mb), "r"(count) : "memory");
}
__device__ __forceinline__ void mbar_expect_tx(uint32_t mb, uint32_t bytes) {
    asm volatile("mbarrier.arrive.expect_tx.shared.b64 _, [%0], %1;"
                 :: "r"(mb), "r"(bytes) : "memory");
}
__device__ __forceinline__ void bulk_g2s(uint32_t sdst, const void* gsrc,
                                         uint32_t bytes, uint32_t mb) {
    asm volatile(
        "cp.async.bulk.shared::cta.global.mbarrier::complete_tx::bytes "
        "[%0], [%1], %2, [%3];"
        :: "r"(sdst), "l"(gsrc), "r"(bytes), "r"(mb) : "memory");
}
__device__ __forceinline__ void mbar_wait(uint32_t mb, uint32_t parity) {
    uint32_t done;
    asm volatile(
        "{\n\t.reg .pred p;\n\t"
        "mbarrier.try_wait.parity.acquire.cta.shared::cta.b64 p, [%1], %2;\n\t"
        "selp.b32 %0, 1, 0, p;\n\t}"
        : "=r"(done) : "r"(mb), "r"(parity) : "memory");
    if (!done) {
        asm volatile(
            "{\n\t.reg .pred P1;\n\t"
            "WL_%=:\n\t"
            "mbarrier.try_wait.parity.acquire.cta.shared::cta.b64 P1, [%0], %1, 0x989680;\n\t"
            "@P1 bra.uni WD_%=;\n\t"
            "bra.uni WL_%=;\n\t"
            "WD_%=:\n\t}"
            :: "r"(mb), "r"(parity) : "memory");
    }
}

// ---- warp MMA primitives ---------------------------------------------------
__device__ __forceinline__ void ldmx4(uint32_t& r0, uint32_t& r1,
                                      uint32_t& r2, uint32_t& r3, uint32_t addr) {
    asm volatile("ldmatrix.sync.aligned.m8n8.x4.shared.b16 {%0,%1,%2,%3}, [%4];"
                 : "=r"(r0), "=r"(r1), "=r"(r2), "=r"(r3) : "r"(addr));
}

// f16 x f16 -> f16-accum MMA: D registers hold packed f16x2 column pairs.
__device__ __forceinline__ void mma16816h(uint32_t& d01, uint32_t& d23,
                                          uint32_t a0, uint32_t a1, uint32_t a2, uint32_t a3,
                                          uint32_t b0, uint32_t b1) {
    asm volatile(
        "mma.sync.aligned.m16n8k16.row.col.f16.f16.f16.f16 "
        "{%0,%1}, {%2,%3,%4,%5}, {%6,%7}, {%0,%1};"
        : "+r"(d01), "+r"(d23)
        : "r"(a0), "r"(a1), "r"(a2), "r"(a3), "r"(b0), "r"(b1));
}

__device__ __forceinline__ uint32_t ex2_h2(uint32_t h) {
    uint32_t r;
    asm("ex2.approx.f16x2 %0, %1;" : "=r"(r) : "r"(h));
    return r;
}
__device__ __forceinline__ uint32_t hadd2(uint32_t a, uint32_t b) {
    uint32_t r;
    asm("add.rn.f16x2 %0, %1, %2;" : "=r"(r) : "r"(a), "r"(b));
    return r;
}
__device__ __forceinline__ float hsum2f(uint32_t h) {
    __half2 v = *reinterpret_cast<__half2*>(&h);
    float2 f = __half22float2(v);
    return f.x + f.y;
}

// ---------------------------------------------------------------------------
// prep_c: one thread per HALF center row (16 floats). Writes the 64B f16
// image row (c*log2e) with chunk swizzle phys = logical ^ ((j>>1)&3), and
// G'_j = G_j + 10 as f16 (half 0 only). Padded rows: zero image, G' = -30000.
// ---------------------------------------------------------------------------
__global__ void prep_c(const float* __restrict__ c,
                       const float* __restrict__ beta, int M, int mpad) {
    int idx  = blockIdx.x * blockDim.x + threadIdx.x;
    int j    = idx >> 1;
    int half = idx & 1;
    if (j >= mpad) return;

    float v[16];
    if (j < M) {
        const float4* cp = reinterpret_cast<const float4*>(c + (size_t)j * D + half * 16);
        #pragma unroll
        for (int q = 0; q < 4; q++) {
            float4 t = cp[q];
            v[4 * q] = t.x; v[4 * q + 1] = t.y; v[4 * q + 2] = t.z; v[4 * q + 3] = t.w;
        }
    } else {
        #pragma unroll
        for (int k = 0; k < 16; k++) v[k] = 0.f;
    }
    float s = 0.f;
    #pragma unroll
    for (int k = 0; k < 16; k++) {
        s = fmaf(v[k], v[k], s);
        v[k] *= LOG2E;
    }
    s += __shfl_xor_sync(0xffffffffu, s, 1);   // full ||c||^2 (pair in same warp)

    uint32_t wd[8];
    #pragma unroll
    for (int k = 0; k < 8; k++) wd[k] = pack_hf2(v[2 * k], v[2 * k + 1]);

    const uint32_t key = ((uint32_t)j >> 1) & 3;
    uint8_t* base = g_cI + (size_t)j * ROWB;
    #pragma unroll
    for (int cch = 0; cch < 2; cch++) {
        uint32_t lch = (uint32_t)half * 2 + cch;
        uint4 u = make_uint4(wd[4 * cch], wd[4 * cch + 1], wd[4 * cch + 2], wd[4 * cch + 3]);
        *reinterpret_cast<uint4*>(base + ((lch ^ key) << 4)) = u;
    }

    if (half == 0) {
        float Gp = (j < M) ? (fmaf(-0.5f * LOG2E, s, log2f(beta[j])) + 10.0f)
                           : -30000.0f;
        g_Gh[j] = __float2half(Gp);
    }
}

// ---------------------------------------------------------------------------
// Main fused kernel: grid = ceil(N/96), 384 threads (12 warps).
// Warp pair (wp = w>>1) owns rows [wp*16, wp*16+16); half = w&1 selects which
// 64 centers of the 128-tile the warp processes.
// smem: A 6KB | B0 8KB | B1 8KB | G0 256B | G1 256B | bx 384B | red 768B | mb
// ---------------------------------------------------------------------------
constexpr int SA   = 0;
constexpr int SB0  = 6144;
constexpr int SB1  = 14336;
constexpr int SG0  = 22528;      // NB halves = 256B
constexpr int SG1  = 22784;
constexpr int SBX  = 23040;      // float[96]
constexpr int SRED = 23424;      // float[2][96]
constexpr int SMB  = 24192;      // mbF0 @+0, mbF1 @+8
constexpr int STOT = 24208;

__global__ void __launch_bounds__(384)
krr_main(const float* __restrict__ x, float* __restrict__ out, int N, int ntiles)
{
    __shared__ __align__(128) uint8_t smem[STOT];
    const uint32_t sbase = (uint32_t)__cvta_generic_to_shared(smem);

    const int tid  = threadIdx.x;
    const int w    = tid >> 5;
    const int lane = tid & 31;
    const int wp   = w >> 1;       // row group 0..5
    const int half = w & 1;        // center half 0/1

    const uint32_t mbF[2] = {sbase + SMB, sbase + SMB + 8};

    if (tid == 0) {
        mbar_init(mbF[0], 1);
        mbar_init(mbF[1], 1);
    }
    asm volatile("fence.proxy.async.shared::cta;" ::: "memory");
    __syncthreads();

    if (tid == 0) {
        mbar_expect_tx(mbF[0], NB * ROWB + NB * 2);
        bulk_g2s(sbase + SB0, g_cI, NB * ROWB, mbF[0]);
        bulk_g2s(sbase + SG0, g_Gh, NB * 2, mbF[0]);
        if (ntiles > 1) {
            mbar_expect_tx(mbF[1], NB * ROWB + NB * 2);
            bulk_g2s(sbase + SB1, g_cI + (size_t)NB * ROWB, NB * ROWB, mbF[1]);
            bulk_g2s(sbase + SG1, g_Gh + NB, NB * 2, mbF[1]);
        }
    }

    // ---- convert this CTA's 96 x-rows into the swizzled f16 A image -------
    if (tid < 192) {
        int r    = tid >> 1;
        int hh   = tid & 1;
        int gr   = blockIdx.x * RC + r;
        if (gr > N - 1) gr = N - 1;

        float v[16];
        const float4* xp = reinterpret_cast<const float4*>(x + (size_t)gr * D + hh * 16);
        #pragma unroll
        for (int q = 0; q < 4; q++) {
            float4 t = xp[q];
            v[4 * q] = t.x; v[4 * q + 1] = t.y; v[4 * q + 2] = t.z; v[4 * q + 3] = t.w;
        }
        float s = 0.f;
        #pragma unroll
        for (int k = 0; k < 16; k++) s = fmaf(v[k], v[k], s);
        s += __shfl_xor_sync(0xffffffffu, s, 1);

        uint32_t wd[8];
        #pragma unroll
        for (int k = 0; k < 8; k++) wd[k] = pack_hf2(v[2 * k], v[2 * k + 1]);

        const uint32_t key = ((uint32_t)r >> 1) & 3;
        uint8_t* abase = smem + SA + r * ROWB;
        #pragma unroll
        for (int cch = 0; cch < 2; cch++) {
            uint32_t lch = (uint32_t)hh * 2 + cch;
            uint4 u = make_uint4(wd[4 * cch], wd[4 * cch + 1], wd[4 * cch + 2], wd[4 * cch + 3]);
            *reinterpret_cast<uint4*>(abase + ((lch ^ key) << 4)) = u;
        }
        if (hh == 0)
            *reinterpret_cast<float*>(smem + SBX + r * 4) = -0.5f * s * LOG2E;
    }
    __syncthreads();

    // ---- A fragments (once per warp) ----
    const uint32_t arow = (uint32_t)wp * 16 + (lane & 15);
    const uint32_t akey = (arow >> 1) & 3;
    uint32_t a[8];
    {
        uint32_t ad0 = sbase + SA + arow * ROWB + ((((uint32_t)(lane >> 4) + 0) ^ akey) << 4);
        uint32_t ad1 = sbase + SA + arow * ROWB + ((((uint32_t)(lane >> 4) + 2) ^ akey) << 4);
        ldmx4(a[0], a[1], a[2], a[3], ad0);   // k 0-15
        ldmx4(a[4], a[5], a[6], a[7], ad1);   // k 16-31
    }

    // per-row bias, packed f16x2 (shift lives in G')
    const float* bxsm = reinterpret_cast<const float*>(smem + SBX);
    const float bxlo = bxsm[wp * 16 + (lane >> 2)];
    const float bxhi = bxsm[wp * 16 + (lane >> 2) + 8];
    const uint32_t bx2lo = pack_hf2(bxlo, bxlo);
    const uint32_t bx2hi = pack_hf2(bxhi, bxhi);

    // per-lane B address constant: row = lane&7, chunk = lane>>3 (swizzled)
    const uint32_t l7 = lane & 7;
    const uint32_t boff = l7 * ROWB + ((((uint32_t)lane >> 3) ^ ((l7 >> 1) & 3)) << 4);
    const uint32_t gbase = (uint32_t)half * 8;   // this warp's first group

    float rs_lo = 0.f, rs_hi = 0.f;

    for (int t = 0; t < ntiles; t++) {
        const int buf = t & 1;
        mbar_wait(mbF[buf], (t >> 1) & 1);

        const uint32_t sB = sbase + (buf ? SB1 : SB0);
        const uint32_t* Gp2 = reinterpret_cast<const uint32_t*>(smem + (buf ? SG1 : SG0));

        uint32_t facc01 = 0u, facc23 = 0u;   // f16x2 window accumulators

        #pragma unroll 4
        for (int gg = 0; gg < 8; gg++) {
            const uint32_t g = gbase + gg;
            uint32_t b0, b1, b2, b3;
            ldmx4(b0, b1, b2, b3, sB + g * (8 * ROWB) + boff);

            // seed: (G'_{c0}, G'_{c1}) + (bx, bx)  [f16x2]
            uint32_t Gpair = Gp2[g * 4 + (lane & 3)];
            uint32_t d01 = hadd2(Gpair, bx2lo);
            uint32_t d23 = hadd2(Gpair, bx2hi);

            mma16816h(d01, d23, a[0], a[1], a[2], a[3], b0, b1);
            mma16816h(d01, d23, a[4], a[5], a[6], a[7], b2, b3);

            facc01 = hadd2(facc01, ex2_h2(d01));
            facc23 = hadd2(facc23, ex2_h2(d23));
        }

        rs_lo += hsum2f(facc01);   // flush 16-term f16 window to f32
        rs_hi += hsum2f(facc23);

        __syncthreads();
        if (tid == 0 && t + 2 < ntiles) {
            mbar_expect_tx(mbF[buf], NB * ROWB + NB * 2);
            bulk_g2s(sbase + (buf ? SB1 : SB0),
                     g_cI + (size_t)(t + 2) * NB * ROWB, NB * ROWB, mbF[buf]);
            bulk_g2s(sbase + (buf ? SG1 : SG0),
                     g_Gh + (size_t)(t + 2) * NB, NB * 2, mbF[buf]);
        }
    }

    // ---- reduce across the 4 column-lanes, deposit per-half partials ----
    rs_lo += __shfl_xor_sync(0xffffffffu, rs_lo, 1);
    rs_lo += __shfl_xor_sync(0xffffffffu, rs_lo, 2);
    rs_hi += __shfl_xor_sync(0xffffffffu, rs_hi, 1);
    rs_hi += __shfl_xor_sync(0xffffffffu, rs_hi, 2);

    float* red = reinterpret_cast<float*>(smem + SRED);
    const int lrow = wp * 16 + (lane >> 2);
    if ((lane & 3) == 0) red[half * 96 + lrow]     = rs_lo;
    if ((lane & 3) == 1) red[half * 96 + lrow + 8] = rs_hi;
    __syncthreads();

    // ---- combine halves, undo 2^10 shift, softplus, write ----
    if (tid < RC) {
        int r = blockIdx.x * RC + tid;
        if (r < N) {
            float s = 0.0009765625f * (red[tid] + red[96 + tid]);   // * 2^-10
            out[r] = s + log1pf(expf(-s));
        }
    }
}

// ---------------------------------------------------------------------------
extern "C" void kernel_launch(void* const* d_in, const int* in_sizes, int n_in,
                              void* d_out, int out_size) {
    const float* x    = (const float*)d_in[0];  // (N, 32)
    const float* c    = (const float*)d_in[1];  // (M, 32)
    const float* beta = (const float*)d_in[2];  // (M,)
    float* out = (float*)d_out;                 // (N,)

    const int M = in_sizes[2];
    const int N = out_size;

    int nct = (M + NB - 1) / NB;
    if (nct > MAXM / NB) nct = MAXM / NB;
    const int mpad = nct * NB;

    prep_c<<<(mpad * 2 + 255) / 256, 256>>>(c, beta, M, mpad);

    const int grid = (N + RC - 1) / RC;
    krr_main<<<grid, 384>>>(x, out, N, nct);
}

// round 10
// speedup vs baseline: 1.3511x; 1.0980x over previous
#include <cuda_runtime.h>
#include <cuda_fp16.h>
#include <cstdint>

// ---------------------------------------------------------------------------
// softplus( exp(-0.5*||x_i - c_j||^2) @ beta ),  N=40000, M=4000, D=32.
//
// R10: R9's f16-accum MMA + packed f16x2 exp, restructured for occupancy:
//  * 576 threads/CTA (18 warps): 6 row-groups x 3 warps, tile NB=192 centers,
//    each warp owns a 64-center third -> ~50 warps/SM at grid 417
//    (imbalance stays 1.065). __launch_bounds__(576,3) pins 3 CTAs/SM.
//  * Inner loop fully unrolled; LDSM addresses are base+imm; per-tile G pairs
//    fetched with two LDS.128 (G re-laid out by prep_c: [tile][colpair][group]).
// ---------------------------------------------------------------------------

#define LOG2E 1.4426950408889634f

constexpr int D     = 32;
constexpr int RC    = 96;        // rows per CTA
constexpr int NB    = 192;       // centers per tile
constexpr int MAXCT = 43;        // max center tiles (M <= 8256)
constexpr int MAXM  = MAXCT * NB;
constexpr int ROWB  = 64;        // bytes per f16 image row (32 f16)
constexpr int GPT   = NB / 2;    // G pairs per tile = 96

__device__ __align__(128) uint8_t g_cI[(size_t)MAXM * ROWB];  // f16(c*log2e), swizzled
__device__ uint32_t g_G2[MAXCT * GPT];  // f16x2 (G'_{2p}, G'_{2p+1}), permuted layout

// pack two f32 into f16x2: lo -> bits[0:16], hi -> bits[16:32]
__device__ __forceinline__ uint32_t pack_hf2(float lo, float hi) {
    uint32_t h;
    asm("cvt.rn.f16x2.f32 %0, %1, %2;" : "=r"(h) : "f"(hi), "f"(lo));
    return h;
}

// ---- async copy / mbarrier -------------------------------------------------
__device__ __forceinline__ void mbar_init(uint32_t mb, int count) {
    asm volatile("mbarrier.init.shared.b64 [%0], %1;" :: "r"(mb), "r"(count) : "memory");
}
__device__ __forceinline__ void mbar_expect_tx(uint32_t mb, uint32_t bytes) {
    asm volatile("mbarrier.arrive.expect_tx.shared.b64 _, [%0], %1;"
                 :: "r"(mb), "r"(bytes) : "memory");
}
__device__ __forceinline__ void bulk_g2s(uint32_t sdst, const void* gsrc,
                                         uint32_t bytes, uint32_t mb) {
    asm volatile(
        "cp.async.bulk.shared::cta.global.mbarrier::complete_tx::bytes "
        "[%0], [%1], %2, [%3];"
        :: "r"(sdst), "l"(gsrc), "r"(bytes), "r"(mb) : "memory");
}
__device__ __forceinline__ void mbar_wait(uint32_t mb, uint32_t parity) {
    uint32_t done;
    asm volatile(
        "{\n\t.reg .pred p;\n\t"
        "mbarrier.try_wait.parity.acquire.cta.shared::cta.b64 p, [%1], %2;\n\t"
        "selp.b32 %0, 1, 0, p;\n\t}"
        : "=r"(done) : "r"(mb), "r"(parity) : "memory");
    if (!done) {
        asm volatile(
            "{\n\t.reg .pred P1;\n\t"
            "WL_%=:\n\t"
            "mbarrier.try_wait.parity.acquire.cta.shared::cta.b64 P1, [%0], %1, 0x989680;\n\t"
            "@P1 bra.uni WD_%=;\n\t"
            "bra.uni WL_%=;\n\t"
            "WD_%=:\n\t}"
            :: "r"(mb), "r"(parity) : "memory");
    }
}

// ---- warp MMA primitives ---------------------------------------------------
__device__ __forceinline__ void ldmx4(uint32_t& r0, uint32_t& r1,
                                      uint32_t& r2, uint32_t& r3, uint32_t addr) {
    asm volatile("ldmatrix.sync.aligned.m8n8.x4.shared.b16 {%0,%1,%2,%3}, [%4];"
                 : "=r"(r0), "=r"(r1), "=r"(r2), "=r"(r3) : "r"(addr));
}

__device__ __forceinline__ void mma16816h(uint32_t& d01, uint32_t& d23,
                                          uint32_t a0, uint32_t a1, uint32_t a2, uint32_t a3,
                                          uint32_t b0, uint32_t b1) {
    asm volatile(
        "mma.sync.aligned.m16n8k16.row.col.f16.f16.f16.f16 "
        "{%0,%1}, {%2,%3,%4,%5}, {%6,%7}, {%0,%1};"
        : "+r"(d01), "+r"(d23)
        : "r"(a0), "r"(a1), "r"(a2), "r"(a3), "r"(b0), "r"(b1));
}

__device__ __forceinline__ uint32_t ex2_h2(uint32_t h) {
    uint32_t r;
    asm("ex2.approx.f16x2 %0, %1;" : "=r"(r) : "r"(h));
    return r;
}
__device__ __forceinline__ uint32_t hadd2(uint32_t a, uint32_t b) {
    uint32_t r;
    asm("add.rn.f16x2 %0, %1, %2;" : "=r"(r) : "r"(a), "r"(b));
    return r;
}
__device__ __forceinline__ float hsum2f(uint32_t h) {
    __half2 v = *reinterpret_cast<__half2*>(&h);
    float2 f = __half22float2(v);
    return f.x + f.y;
}

// ---------------------------------------------------------------------------
// prep_c: one thread per HALF center row. Writes the 64B f16 image row
// (c*log2e, chunk swizzle phys = logical ^ ((j>>1)&3)) and, for even-j lanes,
// the G' pair in the permuted per-tile layout [tile][colpair(0..3)][group(0..23)].
// G' = -0.5||c||^2*log2e + log2(beta) + 10; padded rows: zero image, G' = -30000.
// ---------------------------------------------------------------------------
__global__ void prep_c(const float* __restrict__ c,
                       const float* __restrict__ beta, int M, int mpad) {
    int idx  = blockIdx.x * blockDim.x + threadIdx.x;
    int j    = idx >> 1;
    int half = idx & 1;
    int lane = idx & 31;
    if (j >= mpad) return;

    float v[16];
    if (j < M) {
        const float4* cp = reinterpret_cast<const float4*>(c + (size_t)j * D + half * 16);
        #pragma unroll
        for (int q = 0; q < 4; q++) {
            float4 t = cp[q];
            v[4 * q] = t.x; v[4 * q + 1] = t.y; v[4 * q + 2] = t.z; v[4 * q + 3] = t.w;
        }
    } else {
        #pragma unroll
        for (int k = 0; k < 16; k++) v[k] = 0.f;
    }
    float s = 0.f;
    #pragma unroll
    for (int k = 0; k < 16; k++) {
        s = fmaf(v[k], v[k], s);
        v[k] *= LOG2E;
    }
    s += __shfl_xor_sync(0xffffffffu, s, 1);   // full ||c||^2

    uint32_t wd[8];
    #pragma unroll
    for (int k = 0; k < 8; k++) wd[k] = pack_hf2(v[2 * k], v[2 * k + 1]);

    const uint32_t key = ((uint32_t)j >> 1) & 3;
    uint8_t* base = g_cI + (size_t)j * ROWB;
    #pragma unroll
    for (int cch = 0; cch < 2; cch++) {
        uint32_t lch = (uint32_t)half * 2 + cch;
        uint4 u = make_uint4(wd[4 * cch], wd[4 * cch + 1], wd[4 * cch + 2], wd[4 * cch + 3]);
        *reinterpret_cast<uint4*>(base + ((lch ^ key) << 4)) = u;
    }

    // G' for this center (all lanes compute; only pair-leader stores)
    float Gval = (j < M) ? (fmaf(-0.5f * LOG2E, s, log2f(beta[j])) + 10.0f)
                         : -30000.0f;
    float Gnext = __shfl_down_sync(0xffffffffu, Gval, 2);   // G'(j+1)
    if ((lane & 3) == 0) {      // j even, half 0
        int p  = j >> 1;        // global pair index
        int T  = p / GPT;
        int pi = p - T * GPT;   // 0..95
        g_G2[T * GPT + (pi & 3) * 24 + (pi >> 2)] = pack_hf2(Gval, Gnext);
    }
}

// ---------------------------------------------------------------------------
// Main fused kernel: grid = ceil(N/96), 576 threads (18 warps).
// Warp w: row group wp = w/3 (16 rows), third = w%3 (64 centers of the tile).
// smem: A 6KB | B0 12KB | B1 12KB | G0 384B | G1 384B | bx 384B | red 1152B | mb
// ---------------------------------------------------------------------------
constexpr int SA   = 0;
constexpr int SB0  = 6144;
constexpr int SB1  = 18432;
constexpr int SG0  = 30720;
constexpr int SG1  = 31104;
constexpr int SBX  = 31488;
constexpr int SRED = 31872;          // float[3][96]
constexpr int SMB  = 33024;          // mbF0 @+0, mbF1 @+8
constexpr int STOT = 33040;

__global__ void __launch_bounds__(576, 3)
krr_main(const float* __restrict__ x, float* __restrict__ out, int N, int ntiles)
{
    __shared__ __align__(128) uint8_t smem[STOT];
    const uint32_t sbase = (uint32_t)__cvta_generic_to_shared(smem);

    const int tid   = threadIdx.x;
    const int w     = tid >> 5;
    const int lane  = tid & 31;
    const int wp    = w / 3;        // row group 0..5
    const int third = w - wp * 3;   // center third 0..2

    const uint32_t mbF[2] = {sbase + SMB, sbase + SMB + 8};

    if (tid == 0) {
        mbar_init(mbF[0], 1);
        mbar_init(mbF[1], 1);
    }
    asm volatile("fence.proxy.async.shared::cta;" ::: "memory");
    __syncthreads();

    if (tid == 0) {
        mbar_expect_tx(mbF[0], NB * ROWB + GPT * 4);
        bulk_g2s(sbase + SB0, g_cI, NB * ROWB, mbF[0]);
        bulk_g2s(sbase + SG0, g_G2, GPT * 4, mbF[0]);
        if (ntiles > 1) {
            mbar_expect_tx(mbF[1], NB * ROWB + GPT * 4);
            bulk_g2s(sbase + SB1, g_cI + (size_t)NB * ROWB, NB * ROWB, mbF[1]);
            bulk_g2s(sbase + SG1, g_G2 + GPT, GPT * 4, mbF[1]);
        }
    }

    // ---- convert this CTA's 96 x-rows into the swizzled f16 A image -------
    if (tid < 192) {
        int r  = tid >> 1;
        int hh = tid & 1;
        int gr = blockIdx.x * RC + r;
        if (gr > N - 1) gr = N - 1;

        float v[16];
        const float4* xp = reinterpret_cast<const float4*>(x + (size_t)gr * D + hh * 16);
        #pragma unroll
        for (int q = 0; q < 4; q++) {
            float4 t = xp[q];
            v[4 * q] = t.x; v[4 * q + 1] = t.y; v[4 * q + 2] = t.z; v[4 * q + 3] = t.w;
        }
        float s = 0.f;
        #pragma unroll
        for (int k = 0; k < 16; k++) s = fmaf(v[k], v[k], s);
        s += __shfl_xor_sync(0xffffffffu, s, 1);

        uint32_t wd[8];
        #pragma unroll
        for (int k = 0; k < 8; k++) wd[k] = pack_hf2(v[2 * k], v[2 * k + 1]);

        const uint32_t key = ((uint32_t)r >> 1) & 3;
        uint8_t* abase = smem + SA + r * ROWB;
        #pragma unroll
        for (int cch = 0; cch < 2; cch++) {
            uint32_t lch = (uint32_t)hh * 2 + cch;
            uint4 u = make_uint4(wd[4 * cch], wd[4 * cch + 1], wd[4 * cch + 2], wd[4 * cch + 3]);
            *reinterpret_cast<uint4*>(abase + ((lch ^ key) << 4)) = u;
        }
        if (hh == 0)
            *reinterpret_cast<float*>(smem + SBX + r * 4) = -0.5f * s * LOG2E;
    }
    __syncthreads();

    // ---- A fragments (once per warp) ----
    const uint32_t arow = (uint32_t)wp * 16 + (lane & 15);
    const uint32_t akey = (arow >> 1) & 3;
    uint32_t a[8];
    {
        uint32_t ad0 = sbase + SA + arow * ROWB + ((((uint32_t)(lane >> 4) + 0) ^ akey) << 4);
        uint32_t ad1 = sbase + SA + arow * ROWB + ((((uint32_t)(lane >> 4) + 2) ^ akey) << 4);
        ldmx4(a[0], a[1], a[2], a[3], ad0);   // k 0-15
        ldmx4(a[4], a[5], a[6], a[7], ad1);   // k 16-31
    }

    // per-row bias, packed f16x2 (global 2^10 shift lives in G')
    const float* bxsm = reinterpret_cast<const float*>(smem + SBX);
    const uint32_t bx2lo = pack_hf2(bxsm[wp * 16 + (lane >> 2)],
                                    bxsm[wp * 16 + (lane >> 2)]);
    const uint32_t bx2hi = pack_hf2(bxsm[wp * 16 + (lane >> 2) + 8],
                                    bxsm[wp * 16 + (lane >> 2) + 8]);

    // per-lane B address constant: row = lane&7, chunk = lane>>3 (swizzled)
    const uint32_t l7 = lane & 7;
    const uint32_t boff = l7 * ROWB + ((((uint32_t)lane >> 3) ^ ((l7 >> 1) & 3)) << 4)
                        + (uint32_t)third * 8 * 512;      // this third's groups
    const uint32_t goff = ((uint32_t)(lane & 3) * 24 + (uint32_t)third * 8) * 4;

    float rs_lo = 0.f, rs_hi = 0.f;

    for (int t = 0; t < ntiles; t++) {
        const int buf = t & 1;
        mbar_wait(mbF[buf], (t >> 1) & 1);

        const uint32_t bB = sbase + (buf ? SB1 : SB0) + boff;
        const uint8_t* gBp = smem + (buf ? SG1 : SG0) + goff;

        uint32_t facc01 = 0u, facc23 = 0u;

        // 8 groups, fully unrolled; G pairs via two LDS.128
        uint4 q0 = *reinterpret_cast<const uint4*>(gBp);
        #pragma unroll
        for (int gg = 0; gg < 4; gg++) {
            uint32_t Gpair = (gg == 0) ? q0.x : (gg == 1) ? q0.y : (gg == 2) ? q0.z : q0.w;
            uint32_t b0, b1, b2, b3;
            ldmx4(b0, b1, b2, b3, bB + gg * 512);
            uint32_t d01 = hadd2(Gpair, bx2lo);
            uint32_t d23 = hadd2(Gpair, bx2hi);
            mma16816h(d01, d23, a[0], a[1], a[2], a[3], b0, b1);
            mma16816h(d01, d23, a[4], a[5], a[6], a[7], b2, b3);
            facc01 = hadd2(facc01, ex2_h2(d01));
            facc23 = hadd2(facc23, ex2_h2(d23));
        }
        uint4 q1 = *reinterpret_cast<const uint4*>(gBp + 16);
        #pragma unroll
        for (int gg = 0; gg < 4; gg++) {
            uint32_t Gpair = (gg == 0) ? q1.x : (gg == 1) ? q1.y : (gg == 2) ? q1.z : q1.w;
            uint32_t b0, b1, b2, b3;
            ldmx4(b0, b1, b2, b3, bB + (gg + 4) * 512);
            uint32_t d01 = hadd2(Gpair, bx2lo);
            uint32_t d23 = hadd2(Gpair, bx2hi);
            mma16816h(d01, d23, a[0], a[1], a[2], a[3], b0, b1);
            mma16816h(d01, d23, a[4], a[5], a[6], a[7], b2, b3);
            facc01 = hadd2(facc01, ex2_h2(d01));
            facc23 = hadd2(facc23, ex2_h2(d23));
        }

        rs_lo += hsum2f(facc01);   // flush 16-term f16 window to f32
        rs_hi += hsum2f(facc23);

        __syncthreads();
        if (tid == 0 && t + 2 < ntiles) {
            mbar_expect_tx(mbF[buf], NB * ROWB + GPT * 4);
            bulk_g2s(sbase + (buf ? SB1 : SB0),
                     g_cI + (size_t)(t + 2) * NB * ROWB, NB * ROWB, mbF[buf]);
            bulk_g2s(sbase + (buf ? SG1 : SG0),
                     g_G2 + (size_t)(t + 2) * GPT, GPT * 4, mbF[buf]);
        }
    }

    // ---- reduce across the 4 column-lanes, deposit per-third partials ----
    rs_lo += __shfl_xor_sync(0xffffffffu, rs_lo, 1);
    rs_lo += __shfl_xor_sync(0xffffffffu, rs_lo, 2);
    rs_hi += __shfl_xor_sync(0xffffffffu, rs_hi, 1);
    rs_hi += __shfl_xor_sync(0xffffffffu, rs_hi, 2);

    float* red = reinterpret_cast<float*>(smem + SRED);
    const int lrow = wp * 16 + (lane >> 2);
    if ((lane & 3) == 0) red[third * 96 + lrow]     = rs_lo;
    if ((lane & 3) == 1) red[third * 96 + lrow + 8] = rs_hi;
    __syncthreads();

    // ---- combine thirds, undo 2^10 shift, softplus, write ----
    if (tid < RC) {
        int r = blockIdx.x * RC + tid;
        if (r < N) {
            float s = 0.0009765625f * (red[tid] + red[96 + tid] + red[192 + tid]);
            out[r] = s + log1pf(expf(-s));
        }
    }
}

// ---------------------------------------------------------------------------
extern "C" void kernel_launch(void* const* d_in, const int* in_sizes, int n_in,
                              void* d_out, int out_size) {
    const float* x    = (const float*)d_in[0];  // (N, 32)
    const float* c    = (const float*)d_in[1];  // (M, 32)
    const float* beta = (const float*)d_in[2];  // (M,)
    float* out = (float*)d_out;                 // (N,)

    const int M = in_sizes[2];
    const int N = out_size;

    int nct = (M + NB - 1) / NB;
    if (nct > MAXCT) nct = MAXCT;
    const int mpad = nct * NB;

    prep_c<<<(mpad * 2 + 255) / 256, 256>>>(c, beta, M, mpad);

    const int grid = (N + RC - 1) / RC;
    krr_main<<<grid, 576>>>(x, out, N, nct);
}